// round 16
// baseline (speedup 1.0000x reference)
#include <cuda_runtime.h>

#define BATCH 16
#define LEN   512
#define IDIM  300
#define HDIM  32
#define ODIM  15
#define GDIM  96
#define JH    128         // keys per attn1 block (interleaved mod-4 chunks)
#define NGRP  4           // interleave groups
#define TI1   16          // i-rows per attn1 block
#define KSTR  36          // smem row stride (floats), 16B-aligned
#define ESTR  65          // attn2 e-tile stride (odd -> conflict-free)
#define NKT   19          // gx k-steps (19*16 >= 300)

typedef unsigned long long ull;

// Scratch as float4 arrays (guarantees 16B alignment for vector access)
__device__ float4 g_gx4 [BATCH * LEN * GDIM / 4];
__device__ float4 g_out4[BATCH * LEN * HDIM / 4];
__device__ float4 g_qh4 [BATCH * LEN * HDIM / 4];
__device__ float4 g_kh4 [BATCH * LEN * HDIM / 4];
#define g_gx  ((float*)g_gx4)
#define g_out ((float*)g_out4)
#define g_qh  ((float*)g_qh4)
#define g_kh  ((float*)g_kh4)

__device__ float4 g_e4[BATCH * LEN * LEN / 4];       // raw e scores
#define g_e ((float*)g_e4)
__device__ float g_ps[BATCH * NGRP * LEN];            // per-(row,group) partial sums

__device__ __forceinline__ float tanh_fast(float x) {
    float y;
    asm("tanh.approx.f32 %0, %1;" : "=f"(y) : "f"(x));
    return y;
}
__device__ __forceinline__ ull ffma2u(ull a, ull b, ull c) {
    ull d;
    asm("fma.rn.f32x2 %0, %1, %2, %3;" : "=l"(d) : "l"(a), "l"(b), "l"(c));
    return d;
}
__device__ __forceinline__ ull add2u(ull a, ull b) {
    ull d;
    asm("add.rn.f32x2 %0, %1, %2;" : "=l"(d) : "l"(a), "l"(b));
    return d;
}
__device__ __forceinline__ ull pack2(float lo, float hi) {
    ull d;
    asm("mov.b64 %0, {%1, %2};" : "=l"(d) : "f"(lo), "f"(hi));
    return d;
}
__device__ __forceinline__ float hsum2(ull a) {
    float lo, hi;
    asm("mov.b64 {%0, %1}, %2;" : "=f"(lo), "=f"(hi) : "l"(a));
    return lo + hi;
}

// ---------------------------------------------------------------------------
// K1: gx = x @ w_ih^T + b_ih  (M=8192, N=96, K=300), 64-row tiles,
// double-buffered pipeline (proven R11 version).
// ---------------------------------------------------------------------------
__global__ __launch_bounds__(256) void gx_kernel(
    const float* __restrict__ x,
    const float* __restrict__ w_ih,
    const float* __restrict__ b_ih)
{
    __shared__ float xs[2][16][65];
    __shared__ float ws[2][16][97];

    const int tid = threadIdx.x;
    const int m0 = blockIdx.x * 64;
    const int tx = tid & 15;
    const int ty = tid >> 4;

    const int lr  = tid >> 2;       // load row (x) / col (w rows 0..63)
    const int lc4 = tid & 3;        // float4 slot within 16-k step

    float acc[4][6];
#pragma unroll
    for (int i = 0; i < 4; i++)
#pragma unroll
        for (int j = 0; j < 6; j++) acc[i][j] = 0.f;

    float4 xv, wv0, wv1;
    const float4 z4 = make_float4(0.f, 0.f, 0.f, 0.f);

#define GX_LOAD(IT) do {                                                     \
        const int kt = (IT) * 16;                                            \
        const bool ok = (kt + lc4 * 4 + 3) < IDIM;                           \
        xv  = ok ? *(const float4*)(x + (m0 + lr) * IDIM + kt + lc4 * 4)     \
                 : z4;                                                       \
        wv0 = ok ? *(const float4*)(w_ih + lr * IDIM + kt + lc4 * 4) : z4;   \
        if (tid < 128)                                                       \
            wv1 = ok ? *(const float4*)(w_ih + (64 + lr) * IDIM + kt +       \
                                        lc4 * 4) : z4;                       \
    } while (0)

#define GX_STORE(BUF) do {                                                   \
        xs[BUF][lc4 * 4 + 0][lr] = xv.x;                                     \
        xs[BUF][lc4 * 4 + 1][lr] = xv.y;                                     \
        xs[BUF][lc4 * 4 + 2][lr] = xv.z;                                     \
        xs[BUF][lc4 * 4 + 3][lr] = xv.w;                                     \
        ws[BUF][lc4 * 4 + 0][lr] = wv0.x;                                    \
        ws[BUF][lc4 * 4 + 1][lr] = wv0.y;                                    \
        ws[BUF][lc4 * 4 + 2][lr] = wv0.z;                                    \
        ws[BUF][lc4 * 4 + 3][lr] = wv0.w;                                    \
        if (tid < 128) {                                                     \
            ws[BUF][lc4 * 4 + 0][64 + lr] = wv1.x;                           \
            ws[BUF][lc4 * 4 + 1][64 + lr] = wv1.y;                           \
            ws[BUF][lc4 * 4 + 2][64 + lr] = wv1.z;                           \
            ws[BUF][lc4 * 4 + 3][64 + lr] = wv1.w;                           \
        }                                                                    \
    } while (0)

    GX_LOAD(0);
    GX_STORE(0);
    __syncthreads();

    for (int it = 0; it < NKT; it++) {
        const int cur = it & 1;
        if (it + 1 < NKT) GX_LOAD(it + 1);

#pragma unroll
        for (int kk = 0; kk < 16; kk++) {
            float xvv[4], wvv[6];
#pragma unroll
            for (int i = 0; i < 4; i++) xvv[i] = xs[cur][kk][ty * 4 + i];
#pragma unroll
            for (int j = 0; j < 6; j++) wvv[j] = ws[cur][kk][tx * 6 + j];
#pragma unroll
            for (int i = 0; i < 4; i++)
#pragma unroll
                for (int j = 0; j < 6; j++)
                    acc[i][j] = fmaf(xvv[i], wvv[j], acc[i][j]);
        }
        if (it + 1 < NKT) GX_STORE((it + 1) & 1);
        __syncthreads();
    }

#pragma unroll
    for (int i = 0; i < 4; i++) {
        int m = m0 + ty * 4 + i;
#pragma unroll
        for (int j = 0; j < 6; j++) {
            int c = tx * 6 + j;
            g_gx[m * GDIM + c] = acc[i][j] + b_ih[c];
        }
    }
}

// ---------------------------------------------------------------------------
// K2: GRU recurrence (R14 body). Outer loop in static blocks of 4 steps
// (compile-time inner trip count preserves scheduling); early break when the
// next block starts at/after len; tail zero-filled with vector stores.
// ---------------------------------------------------------------------------
__global__ __launch_bounds__(32) void gru_kernel(
    const float* __restrict__ w_hh,
    const float* __restrict__ b_hh,
    const float* __restrict__ h0,
    const int*   __restrict__ x_lens)
{
    const int b = blockIdx.x;
    const int h = threadIdx.x;

    const ull* w8 = (const ull*)w_hh;   // [96][16] packed pairs
    ull wr2[16], wz2[16], wn2[16];
#pragma unroll
    for (int k = 0; k < 16; k++) {
        wr2[k] = w8[(0 * HDIM + h) * 16 + k];
        wz2[k] = w8[(1 * HDIM + h) * 16 + k];
        wn2[k] = w8[(2 * HDIM + h) * 16 + k];
    }
    const ull brp = pack2(b_hh[h], 0.f);
    const ull bzp = pack2(b_hh[HDIM + h], 0.f);
    const ull bnp = pack2(b_hh[2 * HDIM + h], 0.f);

    float hcur = h0[b * HDIM + h];
    float nb0 = __shfl_xor_sync(0xffffffffu, hcur, 1);
    ull hpair = (h & 1) ? pack2(nb0, hcur) : pack2(hcur, nb0);

    const int len = x_lens[b];
    const float* gxb = g_gx + (size_t)b * LEN * GDIM;
    float* outb = g_out + (size_t)b * LEN * HDIM;

    float rxb[4], zxb[4], nxb[4];
#pragma unroll
    for (int t = 0; t < 4; t++) {
        const float* p = gxb + t * GDIM;
        rxb[t] = p[h]; zxb[t] = p[HDIM + h]; nxb[t] = p[2 * HDIM + h];
    }

    for (int t0 = 0; t0 < LEN; t0 += 4) {
#pragma unroll
        for (int u = 0; u < 4; u++) {
            const int t = t0 + u;
            const int s = u;
            const float rx = rxb[s], zx = zxb[s], nx = nxb[s];
            if (t + 4 < LEN) {
                const float* p = gxb + (t + 4) * GDIM;
                rxb[s] = p[h]; zxb[s] = p[HDIM + h]; nxb[s] = p[2 * HDIM + h];
            }

            ull ra[4] = {brp, 0ull, 0ull, 0ull};
            ull za[4] = {bzp, 0ull, 0ull, 0ull};
            ull na[4] = {bnp, 0ull, 0ull, 0ull};
#pragma unroll
            for (int k = 0; k < 16; k++) {
                const ull h2 = __shfl_sync(0xffffffffu, hpair, 2 * k);
                const int p = k & 3;
                ra[p] = ffma2u(wr2[k], h2, ra[p]);
                za[p] = ffma2u(wz2[k], h2, za[p]);
                na[p] = ffma2u(wn2[k], h2, na[p]);
            }
            const float rh = hsum2(add2u(add2u(ra[0], ra[1]),
                                         add2u(ra[2], ra[3])));
            const float zh = hsum2(add2u(add2u(za[0], za[1]),
                                         add2u(za[2], za[3])));
            const float nh = hsum2(add2u(add2u(na[0], na[1]),
                                         add2u(na[2], na[3])));

            const float r = fmaf(tanh_fast((rx + rh) * 0.5f), 0.5f, 0.5f);
            const float z = fmaf(tanh_fast((zx + zh) * 0.5f), 0.5f, 0.5f);
            const float n = tanh_fast(fmaf(r, nh, nx));
            hcur = fmaf(z, hcur - n, n);

            const float nb = __shfl_xor_sync(0xffffffffu, hcur, 1);
            hpair = (h & 1) ? pack2(nb, hcur) : pack2(hcur, nb);

            if (t < len) outb[t * HDIM + h] = hcur;
        }
        if (t0 + 4 >= len) break;
    }

    // zero masked tail: rows [len, LEN) x 32 floats, float4 stores
    {
        float4* outb4 = (float4*)(outb);
        const float4 z4 = make_float4(0.f, 0.f, 0.f, 0.f);
        for (int idx = len * 8 + h; idx < LEN * 8; idx += 32)
            outb4[idx] = z4;
    }
}

// ---------------------------------------------------------------------------
// K3: qh = out@fch_w^T, kh = out@fco_w^T
// ---------------------------------------------------------------------------
__global__ __launch_bounds__(256) void qk_kernel(
    const float* __restrict__ fch_w,
    const float* __restrict__ fco_w)
{
    __shared__ float wq[HDIM][HDIM + 1];
    __shared__ float wk[HDIM][HDIM + 1];
    __shared__ float os[8][HDIM];

    const int tid = threadIdx.x;
    for (int idx = tid; idx < HDIM * HDIM; idx += 256) {
        int c = idx >> 5, k = idx & 31;
        wq[k][c] = fch_w[c * HDIM + k];
        wk[k][c] = fco_w[c * HDIM + k];
    }
    const int m0 = blockIdx.x * 8;
    const int r = tid >> 5, c = tid & 31;
    os[r][c] = g_out[(m0 + r) * HDIM + c];
    __syncthreads();

    float aq = 0.f, ak = 0.f;
#pragma unroll
    for (int k = 0; k < HDIM; k++) {
        float o = os[r][k];
        aq = fmaf(o, wq[k][c], aq);
        ak = fmaf(o, wk[k][c], ak);
    }
    g_qh[(m0 + r) * HDIM + c] = aq;
    g_kh[(m0 + r) * HDIM + c] = ak;
}

// ---------------------------------------------------------------------------
// K4a: e scores + per-(row,group) exp-sums. Mod-4 interleaved chunks,
// 128-row key tile, TI1=16 (proven R14 version).
// ---------------------------------------------------------------------------
__global__ __launch_bounds__(256, 4) void attn1_kernel(
    const float* __restrict__ v,
    const int*   __restrict__ x_lens)
{
    __shared__ float ks[JH * KSTR];
    __shared__ float vsh[HDIM];

    const int b    = blockIdx.z;
    const int grp  = blockIdx.y;                  // 0..3
    const int i0   = blockIdx.x * TI1;
    const int tid  = threadIdx.x;
    const int wid  = tid >> 5, lane = tid & 31;

    // load interleaved key chunks: local chunk c <-> global chunk 4c+grp
    for (int idx = tid; idx < JH * 8; idx += 256) {
        int jl = idx >> 3, q = idx & 7;
        int jg = ((jl & ~31) << 2) + grp * 32 + (jl & 31);
        *(float4*)(ks + jl * KSTR + q * 4) = g_kh4[(b * LEN + jg) * 8 + q];
    }
    if (tid < HDIM) vsh[tid] = v[tid];
    __syncthreads();

    const int len = x_lens[b];                   // 256..512
    const int vc  = (len + 31) >> 5;             // global valid chunks 8..16
    const int nc  = (vc - grp + 3) >> 2;         // local computed chunks 2..4
    const int ntail = (JH / 32) - nc;            // local all-padded chunks

    const float vl = vsh[lane];
    float S = fabsf(vl);
#pragma unroll
    for (int s = 16; s > 0; s >>= 1)
        S += __shfl_xor_sync(0xffffffffu, S, s);

    for (int ii = wid; ii < TI1; ii += 8) {
        const int i = i0 + ii;
        const size_t row = (size_t)b * LEN + i;

        union { float4 v4[8]; float f[HDIM]; } qu;
#pragma unroll
        for (int q = 0; q < 8; q++)
            qu.v4[q] = g_qh4[row * 8 + q];

        float ep = 0.f;
        if (ntail > 0) {
            ep = vl * tanh_fast(g_qh[row * HDIM + lane]);
#pragma unroll
            for (int s = 16; s > 0; s >>= 1)
                ep += __shfl_xor_sync(0xffffffffu, ep, s);
        }

        float* erow = g_e + row * LEN;
        float ssum = 0.f;
        for (int c = 0; c < nc; c++) {
            const float4* krow4 = (const float4*)(ks + (c * 32 + lane) * KSTR);
            float e = 0.f;
#pragma unroll
            for (int q = 0; q < 8; q++) {
                const float4 k4 = krow4[q];
                e = fmaf(vsh[4 * q + 0], tanh_fast(qu.f[4 * q + 0] + k4.x), e);
                e = fmaf(vsh[4 * q + 1], tanh_fast(qu.f[4 * q + 1] + k4.y), e);
                e = fmaf(vsh[4 * q + 2], tanh_fast(qu.f[4 * q + 2] + k4.z), e);
                e = fmaf(vsh[4 * q + 3], tanh_fast(qu.f[4 * q + 3] + k4.w), e);
            }
            ssum += __expf(e - S);
            erow[(4 * c + grp) * 32 + lane] = e;
        }
        // padded chunks: no store needed (out rows are zero in the ctx GEMM)

#pragma unroll
        for (int s = 16; s > 0; s >>= 1)
            ssum += __shfl_xor_sync(0xffffffffu, ssum, s);
        if (ntail > 0) ssum += (float)(ntail * 32) * __expf(ep - S);
        if (lane == 0) g_ps[(b * NGRP + grp) * LEN + i] = ssum;
    }
}

// ---------------------------------------------------------------------------
// K4b: ctx GEMM, double-buffered tiles (one sync per j-tile), conflict-free
// smem, epilogue ctx = e@out - lse*osum, then fc head.
// ---------------------------------------------------------------------------
__global__ __launch_bounds__(256) void attn2_kernel(
    const float* __restrict__ v,
    const float* __restrict__ fc_w,
    const float* __restrict__ fc_b,
    float* __restrict__ y)
{
    __shared__ float As[2][32 * ESTR];    // e tile, row-major [i][j], stride 65
    __shared__ float Bs[2][64 * KSTR];    // out tile [j][h]
    __shared__ float osum_s[32];
    __shared__ float cxs[32][33];
    __shared__ float fcw[ODIM][33];
    __shared__ float fcbs[16];

    const int b    = blockIdx.y;
    const int i0   = blockIdx.x * 32;
    const int tid  = threadIdx.x;
    const int w    = tid >> 5;            // warp: h-group
    const int lane = tid & 31;            // local i
    const int w4   = w * 4;

    const int eli = tid >> 4, elq = tid & 15;   // e: rows eli, eli+16
    const int olj = tid >> 3, olq = tid & 7;    // out: rows olj, olj+32

    for (int idx = tid; idx < ODIM * HDIM; idx += 256) {
        int o = idx / HDIM, h = idx % HDIM;
        fcw[o][h] = fc_w[idx];
    }
    if (tid < ODIM) fcbs[tid] = fc_b[tid];

    float S = fabsf(v[lane]);
#pragma unroll
    for (int s = 16; s > 0; s >>= 1)
        S += __shfl_xor_sync(0xffffffffu, S, s);

    float acc[4] = {0.f, 0.f, 0.f, 0.f};
    float posum[4] = {0.f, 0.f, 0.f, 0.f};

    float4 ev0, ev1, ov0, ov1;

#define A2_LOAD(JT) do {                                                     \
        const int j0n = (JT) * 64;                                           \
        ev0 = g_e4[(((size_t)b * LEN + i0 + eli) * LEN + j0n) / 4 + elq];    \
        ev1 = g_e4[(((size_t)b * LEN + i0 + 16 + eli) * LEN + j0n) / 4 + elq];\
        ov0 = g_out4[((size_t)b * LEN + j0n + olj) * 8 + olq];               \
        ov1 = g_out4[((size_t)b * LEN + j0n + 32 + olj) * 8 + olq];          \
    } while (0)

#define A2_STORE(BUF) do {                                                   \
        float* a0 = &As[BUF][eli * ESTR + 4 * elq];                          \
        a0[0] = ev0.x; a0[1] = ev0.y; a0[2] = ev0.z; a0[3] = ev0.w;          \
        float* a1 = &As[BUF][(eli + 16) * ESTR + 4 * elq];                   \
        a1[0] = ev1.x; a1[1] = ev1.y; a1[2] = ev1.z; a1[3] = ev1.w;          \
        *(float4*)&Bs[BUF][olj * KSTR + 4 * olq] = ov0;                      \
        *(float4*)&Bs[BUF][(olj + 32) * KSTR + 4 * olq] = ov1;               \
    } while (0)

    A2_LOAD(0);
    A2_STORE(0);
    __syncthreads();

    for (int jt = 0; jt < 8; jt++) {
        const int cur = jt & 1;
        if (jt < 7) A2_LOAD(jt + 1);

#pragma unroll
        for (int c = 0; c < 4; c++)
            posum[c] += Bs[cur][lane * KSTR + w4 + c] +
                        Bs[cur][(lane + 32) * KSTR + w4 + c];

#pragma unroll 8
        for (int jj = 0; jj < 64; jj++) {
            const float ev = As[cur][lane * ESTR + jj];
            const float4 b4 = *(const float4*)&Bs[cur][jj * KSTR + w4];
            acc[0] = fmaf(ev, b4.x, acc[0]);
            acc[1] = fmaf(ev, b4.y, acc[1]);
            acc[2] = fmaf(ev, b4.z, acc[2]);
            acc[3] = fmaf(ev, b4.w, acc[3]);
        }
        if (jt < 7) A2_STORE((jt + 1) & 1);
        __syncthreads();
    }

#pragma unroll
    for (int c = 0; c < 4; c++) {
        float t = posum[c];
#pragma unroll
        for (int s = 16; s > 0; s >>= 1)
            t += __shfl_xor_sync(0xffffffffu, t, s);
        if (lane == 0) osum_s[w4 + c] = t;
    }
    __syncthreads();

    const float ps = g_ps[(b * NGRP + 0) * LEN + i0 + lane] +
                     g_ps[(b * NGRP + 1) * LEN + i0 + lane] +
                     g_ps[(b * NGRP + 2) * LEN + i0 + lane] +
                     g_ps[(b * NGRP + 3) * LEN + i0 + lane];
    const float lse = S + __logf(ps);
#pragma unroll
    for (int c = 0; c < 4; c++)
        cxs[lane][w4 + c] = fmaf(-lse, osum_s[w4 + c], acc[c]);
    __syncthreads();

    for (int idx = tid; idx < 32 * ODIM; idx += 256) {
        const int i2 = idx / ODIM, o = idx % ODIM;
        float r = fcbs[o];
#pragma unroll
        for (int h = 0; h < HDIM; h++)
            r = fmaf(fcw[o][h], cxs[i2][h], r);
        y[((size_t)b * LEN + i0 + i2) * ODIM + o] = r;
    }
}

// ---------------------------------------------------------------------------
extern "C" void kernel_launch(void* const* d_in, const int* in_sizes, int n_in,
                              void* d_out, int out_size)
{
    const float* x      = (const float*)d_in[0];
    const int*   x_lens = (const int*)  d_in[1];
    const float* h0     = (const float*)d_in[2];
    const float* w_ih   = (const float*)d_in[3];
    const float* w_hh   = (const float*)d_in[4];
    const float* b_ih   = (const float*)d_in[5];
    const float* b_hh   = (const float*)d_in[6];
    const float* fc_w   = (const float*)d_in[7];
    const float* fc_b   = (const float*)d_in[8];
    const float* fch_w  = (const float*)d_in[9];
    const float* fco_w  = (const float*)d_in[10];
    const float* v      = (const float*)d_in[11];
    float* y = (float*)d_out;

    gx_kernel <<<(BATCH * LEN) / 64, 256>>>(x, w_ih, b_ih);
    gru_kernel<<<BATCH, 32>>>(w_hh, b_hh, h0, x_lens);
    qk_kernel <<<(BATCH * LEN) / 8, 256>>>(fch_w, fco_w);
    attn1_kernel<<<dim3(LEN / TI1, NGRP, BATCH), 256>>>(v, x_lens);
    attn2_kernel<<<dim3(LEN / 32, BATCH), 256>>>(v, fc_w, fc_b, y);
}

// round 17
// speedup vs baseline: 1.0696x; 1.0696x over previous
#include <cuda_runtime.h>

#define BATCH 16
#define LEN   512
#define IDIM  300
#define HDIM  32
#define ODIM  15
#define GDIM  96
#define JH    128         // keys per attn1 block (interleaved mod-4 chunks)
#define NGRP  4           // interleave groups
#define TI1   16          // i-rows per attn1 block
#define KSTR  36          // smem row stride (floats), 16B-aligned
#define ESTR  65          // attn2 e-tile stride (odd -> conflict-free)
#define NKT   19          // gx k-steps (19*16 >= 300)

typedef unsigned long long ull;

// Scratch as float4 arrays (guarantees 16B alignment for vector access)
__device__ float4 g_gx4 [BATCH * LEN * GDIM / 4];
__device__ float4 g_out4[BATCH * LEN * HDIM / 4];
__device__ float4 g_qh4 [BATCH * LEN * HDIM / 4];
__device__ float4 g_kh4 [BATCH * LEN * HDIM / 4];
#define g_gx  ((float*)g_gx4)
#define g_out ((float*)g_out4)
#define g_qh  ((float*)g_qh4)
#define g_kh  ((float*)g_kh4)

__device__ float4 g_e4[BATCH * LEN * LEN / 4];       // raw e scores
#define g_e ((float*)g_e4)
__device__ float g_ps[BATCH * NGRP * LEN];            // per-(row,group) partial sums

__device__ __forceinline__ float tanh_fast(float x) {
    float y;
    asm("tanh.approx.f32 %0, %1;" : "=f"(y) : "f"(x));
    return y;
}
__device__ __forceinline__ ull ffma2u(ull a, ull b, ull c) {
    ull d;
    asm("fma.rn.f32x2 %0, %1, %2, %3;" : "=l"(d) : "l"(a), "l"(b), "l"(c));
    return d;
}
__device__ __forceinline__ ull add2u(ull a, ull b) {
    ull d;
    asm("add.rn.f32x2 %0, %1, %2;" : "=l"(d) : "l"(a), "l"(b));
    return d;
}
__device__ __forceinline__ ull pack2(float lo, float hi) {
    ull d;
    asm("mov.b64 %0, {%1, %2};" : "=l"(d) : "f"(lo), "f"(hi));
    return d;
}
__device__ __forceinline__ float hsum2(ull a) {
    float lo, hi;
    asm("mov.b64 {%0, %1}, %2;" : "=f"(lo), "=f"(hi) : "l"(a));
    return lo + hi;
}

// ---------------------------------------------------------------------------
// K1: gx = x @ w_ih^T + b_ih  (M=8192, N=96, K=300), 64-row tiles,
// double-buffered pipeline (proven R11 version).
// ---------------------------------------------------------------------------
__global__ __launch_bounds__(256) void gx_kernel(
    const float* __restrict__ x,
    const float* __restrict__ w_ih,
    const float* __restrict__ b_ih)
{
    __shared__ float xs[2][16][65];
    __shared__ float ws[2][16][97];

    const int tid = threadIdx.x;
    const int m0 = blockIdx.x * 64;
    const int tx = tid & 15;
    const int ty = tid >> 4;

    const int lr  = tid >> 2;       // load row (x) / col (w rows 0..63)
    const int lc4 = tid & 3;        // float4 slot within 16-k step

    float acc[4][6];
#pragma unroll
    for (int i = 0; i < 4; i++)
#pragma unroll
        for (int j = 0; j < 6; j++) acc[i][j] = 0.f;

    float4 xv, wv0, wv1;
    const float4 z4 = make_float4(0.f, 0.f, 0.f, 0.f);

#define GX_LOAD(IT) do {                                                     \
        const int kt = (IT) * 16;                                            \
        const bool ok = (kt + lc4 * 4 + 3) < IDIM;                           \
        xv  = ok ? *(const float4*)(x + (m0 + lr) * IDIM + kt + lc4 * 4)     \
                 : z4;                                                       \
        wv0 = ok ? *(const float4*)(w_ih + lr * IDIM + kt + lc4 * 4) : z4;   \
        if (tid < 128)                                                       \
            wv1 = ok ? *(const float4*)(w_ih + (64 + lr) * IDIM + kt +       \
                                        lc4 * 4) : z4;                       \
    } while (0)

#define GX_STORE(BUF) do {                                                   \
        xs[BUF][lc4 * 4 + 0][lr] = xv.x;                                     \
        xs[BUF][lc4 * 4 + 1][lr] = xv.y;                                     \
        xs[BUF][lc4 * 4 + 2][lr] = xv.z;                                     \
        xs[BUF][lc4 * 4 + 3][lr] = xv.w;                                     \
        ws[BUF][lc4 * 4 + 0][lr] = wv0.x;                                    \
        ws[BUF][lc4 * 4 + 1][lr] = wv0.y;                                    \
        ws[BUF][lc4 * 4 + 2][lr] = wv0.z;                                    \
        ws[BUF][lc4 * 4 + 3][lr] = wv0.w;                                    \
        if (tid < 128) {                                                     \
            ws[BUF][lc4 * 4 + 0][64 + lr] = wv1.x;                           \
            ws[BUF][lc4 * 4 + 1][64 + lr] = wv1.y;                           \
            ws[BUF][lc4 * 4 + 2][64 + lr] = wv1.z;                           \
            ws[BUF][lc4 * 4 + 3][64 + lr] = wv1.w;                           \
        }                                                                    \
    } while (0)

    GX_LOAD(0);
    GX_STORE(0);
    __syncthreads();

    for (int it = 0; it < NKT; it++) {
        const int cur = it & 1;
        if (it + 1 < NKT) GX_LOAD(it + 1);

#pragma unroll
        for (int kk = 0; kk < 16; kk++) {
            float xvv[4], wvv[6];
#pragma unroll
            for (int i = 0; i < 4; i++) xvv[i] = xs[cur][kk][ty * 4 + i];
#pragma unroll
            for (int j = 0; j < 6; j++) wvv[j] = ws[cur][kk][tx * 6 + j];
#pragma unroll
            for (int i = 0; i < 4; i++)
#pragma unroll
                for (int j = 0; j < 6; j++)
                    acc[i][j] = fmaf(xvv[i], wvv[j], acc[i][j]);
        }
        if (it + 1 < NKT) GX_STORE((it + 1) & 1);
        __syncthreads();
    }

#pragma unroll
    for (int i = 0; i < 4; i++) {
        int m = m0 + ty * 4 + i;
#pragma unroll
        for (int j = 0; j < 6; j++) {
            int c = tx * 6 + j;
            g_gx[m * GDIM + c] = acc[i][j] + b_ih[c];
        }
    }
}

// ---------------------------------------------------------------------------
// K2: GRU recurrence (proven R7/R14 version — do not touch control flow)
// ---------------------------------------------------------------------------
__global__ __launch_bounds__(32) void gru_kernel(
    const float* __restrict__ w_hh,
    const float* __restrict__ b_hh,
    const float* __restrict__ h0,
    const int*   __restrict__ x_lens)
{
    const int b = blockIdx.x;
    const int h = threadIdx.x;

    const ull* w8 = (const ull*)w_hh;   // [96][16] packed pairs
    ull wr2[16], wz2[16], wn2[16];
#pragma unroll
    for (int k = 0; k < 16; k++) {
        wr2[k] = w8[(0 * HDIM + h) * 16 + k];
        wz2[k] = w8[(1 * HDIM + h) * 16 + k];
        wn2[k] = w8[(2 * HDIM + h) * 16 + k];
    }
    const ull brp = pack2(b_hh[h], 0.f);
    const ull bzp = pack2(b_hh[HDIM + h], 0.f);
    const ull bnp = pack2(b_hh[2 * HDIM + h], 0.f);

    float hcur = h0[b * HDIM + h];
    float nb0 = __shfl_xor_sync(0xffffffffu, hcur, 1);
    ull hpair = (h & 1) ? pack2(nb0, hcur) : pack2(hcur, nb0);

    const int len = x_lens[b];
    const float* gxb = g_gx + (size_t)b * LEN * GDIM;
    float* outb = g_out + (size_t)b * LEN * HDIM;

    float rxb[4], zxb[4], nxb[4];
#pragma unroll
    for (int t = 0; t < 4; t++) {
        const float* p = gxb + t * GDIM;
        rxb[t] = p[h]; zxb[t] = p[HDIM + h]; nxb[t] = p[2 * HDIM + h];
    }

#pragma unroll 4
    for (int t = 0; t < LEN; t++) {
        const int s = t & 3;
        const float rx = rxb[s], zx = zxb[s], nx = nxb[s];
        if (t + 4 < LEN) {
            const float* p = gxb + (t + 4) * GDIM;
            rxb[s] = p[h]; zxb[s] = p[HDIM + h]; nxb[s] = p[2 * HDIM + h];
        }

        ull ra[4] = {brp, 0ull, 0ull, 0ull};
        ull za[4] = {bzp, 0ull, 0ull, 0ull};
        ull na[4] = {bnp, 0ull, 0ull, 0ull};
#pragma unroll
        for (int k = 0; k < 16; k++) {
            const ull h2 = __shfl_sync(0xffffffffu, hpair, 2 * k);
            const int p = k & 3;
            ra[p] = ffma2u(wr2[k], h2, ra[p]);
            za[p] = ffma2u(wz2[k], h2, za[p]);
            na[p] = ffma2u(wn2[k], h2, na[p]);
        }
        const float rh = hsum2(add2u(add2u(ra[0], ra[1]), add2u(ra[2], ra[3])));
        const float zh = hsum2(add2u(add2u(za[0], za[1]), add2u(za[2], za[3])));
        const float nh = hsum2(add2u(add2u(na[0], na[1]), add2u(na[2], na[3])));

        const float r = fmaf(tanh_fast((rx + rh) * 0.5f), 0.5f, 0.5f);
        const float z = fmaf(tanh_fast((zx + zh) * 0.5f), 0.5f, 0.5f);
        const float n = tanh_fast(fmaf(r, nh, nx));
        hcur = fmaf(z, hcur - n, n);

        const float nb = __shfl_xor_sync(0xffffffffu, hcur, 1);
        hpair = (h & 1) ? pack2(nb, hcur) : pack2(hcur, nb);

        outb[t * HDIM + h] = (t < len) ? hcur : 0.f;
    }
}

// ---------------------------------------------------------------------------
// K3: qh = out@fch_w^T, kh = out@fco_w^T
// ---------------------------------------------------------------------------
__global__ __launch_bounds__(256) void qk_kernel(
    const float* __restrict__ fch_w,
    const float* __restrict__ fco_w)
{
    __shared__ float wq[HDIM][HDIM + 1];
    __shared__ float wk[HDIM][HDIM + 1];
    __shared__ float os[8][HDIM];

    const int tid = threadIdx.x;
    for (int idx = tid; idx < HDIM * HDIM; idx += 256) {
        int c = idx >> 5, k = idx & 31;
        wq[k][c] = fch_w[c * HDIM + k];
        wk[k][c] = fco_w[c * HDIM + k];
    }
    const int m0 = blockIdx.x * 8;
    const int r = tid >> 5, c = tid & 31;
    os[r][c] = g_out[(m0 + r) * HDIM + c];
    __syncthreads();

    float aq = 0.f, ak = 0.f;
#pragma unroll
    for (int k = 0; k < HDIM; k++) {
        float o = os[r][k];
        aq = fmaf(o, wq[k][c], aq);
        ak = fmaf(o, wk[k][c], ak);
    }
    g_qh[(m0 + r) * HDIM + c] = aq;
    g_kh[(m0 + r) * HDIM + c] = ak;
}

// ---------------------------------------------------------------------------
// K4a: e scores + per-(row,group) exp-sums. Mod-4 interleaved chunks,
// 128-row key tile, TI1=16. e-accumulation split into 4 independent
// chains (8-deep each) to cut the 128-cycle serial FMA chain.
// ---------------------------------------------------------------------------
__global__ __launch_bounds__(256, 4) void attn1_kernel(
    const float* __restrict__ v,
    const int*   __restrict__ x_lens)
{
    __shared__ float ks[JH * KSTR];
    __shared__ float vsh[HDIM];

    const int b    = blockIdx.z;
    const int grp  = blockIdx.y;                  // 0..3
    const int i0   = blockIdx.x * TI1;
    const int tid  = threadIdx.x;
    const int wid  = tid >> 5, lane = tid & 31;

    // load interleaved key chunks: local chunk c <-> global chunk 4c+grp
    for (int idx = tid; idx < JH * 8; idx += 256) {
        int jl = idx >> 3, q = idx & 7;
        int jg = ((jl & ~31) << 2) + grp * 32 + (jl & 31);
        *(float4*)(ks + jl * KSTR + q * 4) = g_kh4[(b * LEN + jg) * 8 + q];
    }
    if (tid < HDIM) vsh[tid] = v[tid];
    __syncthreads();

    const int len = x_lens[b];                   // 256..512
    const int vc  = (len + 31) >> 5;             // global valid chunks 8..16
    const int nc  = (vc - grp + 3) >> 2;         // local computed chunks 2..4
    const int ntail = (JH / 32) - nc;            // local all-padded chunks

    const float vl = vsh[lane];
    float S = fabsf(vl);
#pragma unroll
    for (int s = 16; s > 0; s >>= 1)
        S += __shfl_xor_sync(0xffffffffu, S, s);

    for (int ii = wid; ii < TI1; ii += 8) {
        const int i = i0 + ii;
        const size_t row = (size_t)b * LEN + i;

        union { float4 v4[8]; float f[HDIM]; } qu;
#pragma unroll
        for (int q = 0; q < 8; q++)
            qu.v4[q] = g_qh4[row * 8 + q];

        float ep = 0.f;
        if (ntail > 0) {
            ep = vl * tanh_fast(g_qh[row * HDIM + lane]);
#pragma unroll
            for (int s = 16; s > 0; s >>= 1)
                ep += __shfl_xor_sync(0xffffffffu, ep, s);
        }

        float* erow = g_e + row * LEN;
        float ssum = 0.f;
        for (int c = 0; c < nc; c++) {
            const float4* krow4 = (const float4*)(ks + (c * 32 + lane) * KSTR);
            float e0 = 0.f, e1 = 0.f, e2 = 0.f, e3 = 0.f;
#pragma unroll
            for (int q = 0; q < 8; q++) {
                const float4 k4 = krow4[q];
                e0 = fmaf(vsh[4 * q + 0], tanh_fast(qu.f[4 * q + 0] + k4.x), e0);
                e1 = fmaf(vsh[4 * q + 1], tanh_fast(qu.f[4 * q + 1] + k4.y), e1);
                e2 = fmaf(vsh[4 * q + 2], tanh_fast(qu.f[4 * q + 2] + k4.z), e2);
                e3 = fmaf(vsh[4 * q + 3], tanh_fast(qu.f[4 * q + 3] + k4.w), e3);
            }
            const float e = (e0 + e1) + (e2 + e3);
            ssum += __expf(e - S);
            erow[(4 * c + grp) * 32 + lane] = e;
        }
        // padded chunks: no store needed (out rows are zero in the ctx GEMM)

#pragma unroll
        for (int s = 16; s > 0; s >>= 1)
            ssum += __shfl_xor_sync(0xffffffffu, ssum, s);
        if (ntail > 0) ssum += (float)(ntail * 32) * __expf(ep - S);
        if (lane == 0) g_ps[(b * NGRP + grp) * LEN + i] = ssum;
    }
}

// ---------------------------------------------------------------------------
// K4b: ctx GEMM, double-buffered tiles (one sync per j-tile), conflict-free
// smem, epilogue ctx = e@out - lse*osum, then fc head.
// ---------------------------------------------------------------------------
__global__ __launch_bounds__(256) void attn2_kernel(
    const float* __restrict__ v,
    const float* __restrict__ fc_w,
    const float* __restrict__ fc_b,
    float* __restrict__ y)
{
    __shared__ float As[2][32 * ESTR];    // e tile, row-major [i][j], stride 65
    __shared__ float Bs[2][64 * KSTR];    // out tile [j][h]
    __shared__ float osum_s[32];
    __shared__ float cxs[32][33];
    __shared__ float fcw[ODIM][33];
    __shared__ float fcbs[16];

    const int b    = blockIdx.y;
    const int i0   = blockIdx.x * 32;
    const int tid  = threadIdx.x;
    const int w    = tid >> 5;            // warp: h-group
    const int lane = tid & 31;            // local i
    const int w4   = w * 4;

    const int eli = tid >> 4, elq = tid & 15;   // e: rows eli, eli+16
    const int olj = tid >> 3, olq = tid & 7;    // out: rows olj, olj+32

    for (int idx = tid; idx < ODIM * HDIM; idx += 256) {
        int o = idx / HDIM, h = idx % HDIM;
        fcw[o][h] = fc_w[idx];
    }
    if (tid < ODIM) fcbs[tid] = fc_b[tid];

    float S = fabsf(v[lane]);
#pragma unroll
    for (int s = 16; s > 0; s >>= 1)
        S += __shfl_xor_sync(0xffffffffu, S, s);

    float acc[4] = {0.f, 0.f, 0.f, 0.f};
    float posum[4] = {0.f, 0.f, 0.f, 0.f};

    float4 ev0, ev1, ov0, ov1;

#define A2_LOAD(JT) do {                                                     \
        const int j0n = (JT) * 64;                                           \
        ev0 = g_e4[(((size_t)b * LEN + i0 + eli) * LEN + j0n) / 4 + elq];    \
        ev1 = g_e4[(((size_t)b * LEN + i0 + 16 + eli) * LEN + j0n) / 4 + elq];\
        ov0 = g_out4[((size_t)b * LEN + j0n + olj) * 8 + olq];               \
        ov1 = g_out4[((size_t)b * LEN + j0n + 32 + olj) * 8 + olq];          \
    } while (0)

#define A2_STORE(BUF) do {                                                   \
        float* a0 = &As[BUF][eli * ESTR + 4 * elq];                          \
        a0[0] = ev0.x; a0[1] = ev0.y; a0[2] = ev0.z; a0[3] = ev0.w;          \
        float* a1 = &As[BUF][(eli + 16) * ESTR + 4 * elq];                   \
        a1[0] = ev1.x; a1[1] = ev1.y; a1[2] = ev1.z; a1[3] = ev1.w;          \
        *(float4*)&Bs[BUF][olj * KSTR + 4 * olq] = ov0;                      \
        *(float4*)&Bs[BUF][(olj + 32) * KSTR + 4 * olq] = ov1;               \
    } while (0)

    A2_LOAD(0);
    A2_STORE(0);
    __syncthreads();

    for (int jt = 0; jt < 8; jt++) {
        const int cur = jt & 1;
        if (jt < 7) A2_LOAD(jt + 1);

#pragma unroll
        for (int c = 0; c < 4; c++)
            posum[c] += Bs[cur][lane * KSTR + w4 + c] +
                        Bs[cur][(lane + 32) * KSTR + w4 + c];

#pragma unroll 8
        for (int jj = 0; jj < 64; jj++) {
            const float ev = As[cur][lane * ESTR + jj];
            const float4 b4 = *(const float4*)&Bs[cur][jj * KSTR + w4];
            acc[0] = fmaf(ev, b4.x, acc[0]);
            acc[1] = fmaf(ev, b4.y, acc[1]);
            acc[2] = fmaf(ev, b4.z, acc[2]);
            acc[3] = fmaf(ev, b4.w, acc[3]);
        }
        if (jt < 7) A2_STORE((jt + 1) & 1);
        __syncthreads();
    }

#pragma unroll
    for (int c = 0; c < 4; c++) {
        float t = posum[c];
#pragma unroll
        for (int s = 16; s > 0; s >>= 1)
            t += __shfl_xor_sync(0xffffffffu, t, s);
        if (lane == 0) osum_s[w4 + c] = t;
    }
    __syncthreads();

    const float ps = g_ps[(b * NGRP + 0) * LEN + i0 + lane] +
                     g_ps[(b * NGRP + 1) * LEN + i0 + lane] +
                     g_ps[(b * NGRP + 2) * LEN + i0 + lane] +
                     g_ps[(b * NGRP + 3) * LEN + i0 + lane];
    const float lse = S + __logf(ps);
#pragma unroll
    for (int c = 0; c < 4; c++)
        cxs[lane][w4 + c] = fmaf(-lse, osum_s[w4 + c], acc[c]);
    __syncthreads();

    for (int idx = tid; idx < 32 * ODIM; idx += 256) {
        const int i2 = idx / ODIM, o = idx % ODIM;
        float r = fcbs[o];
#pragma unroll
        for (int h = 0; h < HDIM; h++)
            r = fmaf(fcw[o][h], cxs[i2][h], r);
        y[((size_t)b * LEN + i0 + i2) * ODIM + o] = r;
    }
}

// ---------------------------------------------------------------------------
extern "C" void kernel_launch(void* const* d_in, const int* in_sizes, int n_in,
                              void* d_out, int out_size)
{
    const float* x      = (const float*)d_in[0];
    const int*   x_lens = (const int*)  d_in[1];
    const float* h0     = (const float*)d_in[2];
    const float* w_ih   = (const float*)d_in[3];
    const float* w_hh   = (const float*)d_in[4];
    const float* b_ih   = (const float*)d_in[5];
    const float* b_hh   = (const float*)d_in[6];
    const float* fc_w   = (const float*)d_in[7];
    const float* fc_b   = (const float*)d_in[8];
    const float* fch_w  = (const float*)d_in[9];
    const float* fco_w  = (const float*)d_in[10];
    const float* v      = (const float*)d_in[11];
    float* y = (float*)d_out;

    gx_kernel <<<(BATCH * LEN) / 64, 256>>>(x, w_ih, b_ih);
    gru_kernel<<<BATCH, 32>>>(w_hh, b_hh, h0, x_lens);
    qk_kernel <<<(BATCH * LEN) / 8, 256>>>(fch_w, fco_w);
    attn1_kernel<<<dim3(LEN / TI1, NGRP, BATCH), 256>>>(v, x_lens);
    attn2_kernel<<<dim3(LEN / 32, BATCH), 256>>>(v, fc_w, fc_b, y);
}